// round 1
// baseline (speedup 1.0000x reference)
#include <cuda_runtime.h>
#include <math.h>

// Problem constants
#define NB 4
#define NTT 1024
#define NH 1024
#define NF 4096
#define NE 8
#define NTOK (NB*NTT)        // 4096
#define CAPE (NTOK/NE)       // 512
#define MAXTILES 64

// Scratch (static device allocations are the sanctioned workaround)
__device__ __align__(16) float g_h[(size_t)NTOK * NF];   // 64 MB hidden activations, grouped rows
__device__ int g_prim[NTOK];
__device__ int g_sec[NTOK];
__device__ int g_gather[NTOK];       // grouped row -> token index
__device__ int g_goff[10];           // group offsets (9 groups: experts 0..7, fallback 8)
__device__ int g_ntiles;
__device__ int g_tile_group[MAXTILES];
__device__ int g_tile_row[MAXTILES]; // start row (in grouped space) of each 128-row tile

// ---------------------------------------------------------------------------
// Router: one block per token, 8 warps = 8 experts, warp-reduced dot products.
// top-2 indices of logits == top-2 of softmax (monotone).
// ---------------------------------------------------------------------------
__global__ __launch_bounds__(256) void router_kernel(
    const float* __restrict__ x, const float* __restrict__ rw,
    const float* __restrict__ rb)
{
    int n = blockIdx.x;
    __shared__ float s_log[NE];
    int wid = threadIdx.x >> 5, lane = threadIdx.x & 31;
    const float* xr = x + (size_t)n * NH;
    const float* wr = rw + (size_t)wid * NH;
    float s = 0.f;
    #pragma unroll 8
    for (int k = lane; k < NH; k += 32) s += xr[k] * wr[k];
    #pragma unroll
    for (int o = 16; o; o >>= 1) s += __shfl_xor_sync(0xffffffffu, s, o);
    if (lane == 0) s_log[wid] = s + rb[wid];
    __syncthreads();
    if (threadIdx.x == 0) {
        float b0 = -INFINITY; int i0 = 0;
        #pragma unroll
        for (int e = 0; e < NE; e++) { float v = s_log[e]; if (v > b0) { b0 = v; i0 = e; } }
        float b1 = -INFINITY; int i1 = 0;
        #pragma unroll
        for (int e = 0; e < NE; e++) { if (e == i0) continue; float v = s_log[e]; if (v > b1) { b1 = v; i1 = e; } }
        g_prim[n] = i0; g_sec[n] = i1;
    }
}

// ---------------------------------------------------------------------------
// Capacity assignment: exact reference semantics.
//   pass1: per-expert running count over tokens (order = token index);
//          keep_primary = pos < cap; used[e] = min(count,cap)
//   pass2: overflow tokens scanned per second-expert; take2 = used+pos2 < cap
//   pass3/4: group counts, offsets, tile list, stable gather scatter
// One block, 10 warps; warp e owns expert/group e via ballot prefix scans.
// ---------------------------------------------------------------------------
__global__ __launch_bounds__(320) void assign_kernel()
{
    __shared__ unsigned char s_prim[NTOK], s_sec[NTOK], s_keep[NTOK], s_assign[NTOK];
    __shared__ int s_used[NE], s_gcnt[9], s_goff[10];
    int tid = threadIdx.x;
    int wid = tid >> 5, lane = tid & 31;
    unsigned lmask = (1u << lane) - 1u;

    for (int t = tid; t < NTOK; t += blockDim.x) {
        s_prim[t] = (unsigned char)g_prim[t];
        s_sec[t]  = (unsigned char)g_sec[t];
    }
    __syncthreads();

    // pass 1: primary capacity
    if (wid < NE) {
        int e = wid, run = 0;
        for (int c = 0; c < NTOK; c += 32) {
            int t = c + lane;
            bool bit = (s_prim[t] == e);
            unsigned m = __ballot_sync(0xffffffffu, bit);
            if (bit) {
                int pos = run + __popc(m & lmask);
                bool keep = pos < CAPE;
                s_keep[t]   = keep ? 1 : 0;
                s_assign[t] = keep ? (unsigned char)e : (unsigned char)255;
            }
            run += __popc(m);
        }
        if (lane == 0) s_used[e] = run < CAPE ? run : CAPE;
    }
    __syncthreads();

    // pass 2: second-choice for overflow tokens
    if (wid < NE) {
        int e = wid, run = 0, used = s_used[e];
        for (int c = 0; c < NTOK; c += 32) {
            int t = c + lane;
            bool bit = (s_sec[t] == e) && (s_keep[t] == 0);
            unsigned m = __ballot_sync(0xffffffffu, bit);
            if (bit) {
                int pos2 = run + __popc(m & lmask);
                bool take2 = (used + pos2) < CAPE;
                s_assign[t] = take2 ? (unsigned char)e : (unsigned char)8;
            }
            run += __popc(m);
        }
    }
    __syncthreads();

    // pass 3: group counts (9 groups)
    if (wid < 9) {
        int g = wid, run = 0;
        for (int c = 0; c < NTOK; c += 32) {
            int t = c + lane;
            bool bit = (s_assign[t] == g);
            unsigned m = __ballot_sync(0xffffffffu, bit);
            run += __popc(m);
        }
        if (lane == 0) s_gcnt[g] = run;
    }
    __syncthreads();

    if (tid == 0) {
        s_goff[0] = 0;
        for (int g = 0; g < 9; g++) s_goff[g + 1] = s_goff[g] + s_gcnt[g];
        int nt = 0;
        for (int g = 0; g < 9; g++)
            for (int r = s_goff[g]; r < s_goff[g + 1]; r += 128) {
                g_tile_group[nt] = g; g_tile_row[nt] = r; nt++;
            }
        g_ntiles = nt;
        for (int g = 0; g < 10; g++) g_goff[g] = s_goff[g];
    }
    __syncthreads();

    // pass 4: stable scatter into gather list
    if (wid < 9) {
        int g = wid, run = 0, base = s_goff[g];
        for (int c = 0; c < NTOK; c += 32) {
            int t = c + lane;
            bool bit = (s_assign[t] == g);
            unsigned m = __ballot_sync(0xffffffffu, bit);
            if (bit) g_gather[base + run + __popc(m & lmask)] = t;
            run += __popc(m);
        }
    }
}

// ---------------------------------------------------------------------------
// Grouped SGEMM, 128x128x8 tile, 256 threads, 8x8 microtile.
// FIRST=true : C[r,:] = gelu( x[gather[r],:] @ W1_g + b1_g )  -> g_h  (K=NH, N=NF)
// FIRST=false: out[gather[r],:] = g_h[r,:] @ W2_g + b2_g                (K=NF, N=NH)
// Group 8 uses the shared fallback weights.
// ---------------------------------------------------------------------------
template<int KDIM, int NDIM, bool FIRST>
__global__ __launch_bounds__(256) void moe_gemm(
    const float* __restrict__ Aglob,   // x (FIRST) / unused
    const float* __restrict__ Wexp,
    const float* __restrict__ Wfb,
    const float* __restrict__ Bexp,
    const float* __restrict__ Bfb,
    float* __restrict__ Cout)          // unused (FIRST) / output
{
    int tileIdx = blockIdx.y;
    if (tileIdx >= g_ntiles) return;
    int g    = g_tile_group[tileIdx];
    int row0 = g_tile_row[tileIdx];
    int rend = g_goff[g + 1];
    const float* W    = (g < NE) ? (Wexp + (size_t)g * KDIM * NDIM) : Wfb;
    const float* bias = (g < NE) ? (Bexp + (size_t)g * NDIM) : Bfb;
    int n0 = blockIdx.x * 128;

    __shared__ float As[8][128];
    __shared__ float Bs[8][128];
    __shared__ int rowIdx[128];

    int tid = threadIdx.x;
    if (tid < 128) {
        int r = row0 + tid;
        rowIdx[tid] = (r < rend) ? g_gather[r] : -1;
    }
    __syncthreads();

    int tx = tid & 15, ty = tid >> 4;
    int arow = tid >> 1;             // 0..127
    int acol = (tid & 1) * 4;        // 0 or 4
    int brow = tid >> 5;             // 0..7
    int bcol = (tid & 31) * 4;       // 0..124

    // A row pointer (fixed across K loop)
    const float* aptr = nullptr;
    if (FIRST) {
        int tok = rowIdx[arow];
        if (tok >= 0) aptr = Aglob + (size_t)tok * KDIM;
    } else {
        int r = row0 + arow;
        if (r < rend) aptr = g_h + (size_t)r * KDIM;
    }

    float acc[8][8];
    #pragma unroll
    for (int i = 0; i < 8; i++)
        #pragma unroll
        for (int j = 0; j < 8; j++) acc[i][j] = 0.f;

    for (int k0 = 0; k0 < KDIM; k0 += 8) {
        float4 av = make_float4(0.f, 0.f, 0.f, 0.f);
        if (aptr) av = *(const float4*)(aptr + k0 + acol);
        As[acol + 0][arow] = av.x;
        As[acol + 1][arow] = av.y;
        As[acol + 2][arow] = av.z;
        As[acol + 3][arow] = av.w;
        float4 bv = *(const float4*)(W + (size_t)(k0 + brow) * NDIM + n0 + bcol);
        *(float4*)&Bs[brow][bcol] = bv;
        __syncthreads();
        #pragma unroll
        for (int kk = 0; kk < 8; kk++) {
            float4 a0 = *(const float4*)&As[kk][ty * 8];
            float4 a1 = *(const float4*)&As[kk][ty * 8 + 4];
            float4 b0 = *(const float4*)&Bs[kk][tx * 8];
            float4 b1 = *(const float4*)&Bs[kk][tx * 8 + 4];
            float a[8] = {a0.x, a0.y, a0.z, a0.w, a1.x, a1.y, a1.z, a1.w};
            float b[8] = {b0.x, b0.y, b0.z, b0.w, b1.x, b1.y, b1.z, b1.w};
            #pragma unroll
            for (int i = 0; i < 8; i++)
                #pragma unroll
                for (int j = 0; j < 8; j++) acc[i][j] += a[i] * b[j];
        }
        __syncthreads();
    }

    // epilogue
    #pragma unroll
    for (int i = 0; i < 8; i++) {
        int lr = ty * 8 + i;
        int r = row0 + lr;
        if (r >= rend) continue;
        float* dst;
        if (FIRST) {
            dst = g_h + (size_t)r * NDIM + n0 + tx * 8;
        } else {
            int tok = rowIdx[lr];
            dst = Cout + (size_t)tok * NDIM + n0 + tx * 8;
        }
        #pragma unroll
        for (int j = 0; j < 8; j++) {
            float v = acc[i][j] + bias[n0 + tx * 8 + j];
            if (FIRST) v = 0.5f * v * (1.0f + erff(v * 0.70710678118654752f)); // exact gelu
            dst[j] = v;
        }
    }
}

// ---------------------------------------------------------------------------
extern "C" void kernel_launch(void* const* d_in, const int* in_sizes, int n_in,
                              void* d_out, int out_size)
{
    const float* x   = (const float*)d_in[0];
    const float* rw  = (const float*)d_in[1];
    const float* rb  = (const float*)d_in[2];
    const float* w1  = (const float*)d_in[3];
    const float* b1  = (const float*)d_in[4];
    const float* w2  = (const float*)d_in[5];
    const float* b2  = (const float*)d_in[6];
    const float* sw1 = (const float*)d_in[7];
    const float* sb1 = (const float*)d_in[8];
    const float* sw2 = (const float*)d_in[9];
    const float* sb2 = (const float*)d_in[10];
    float* out = (float*)d_out;

    router_kernel<<<NTOK, 256>>>(x, rw, rb);
    assign_kernel<<<1, 320>>>();
    // GEMM1: x @ w1 -> gelu -> g_h    (K=1024, N=4096)
    moe_gemm<NH, NF, true><<<dim3(NF / 128, 40), 256>>>(x, w1, sw1, b1, sb1, nullptr);
    // GEMM2: g_h @ w2 -> out           (K=4096, N=1024)
    moe_gemm<NF, NH, false><<<dim3(NH / 128, 40), 256>>>(nullptr, w2, sw2, b2, sb2, out);
}

// round 3
// speedup vs baseline: 1.9760x; 1.9760x over previous
#include <cuda_runtime.h>
#include <cuda_bf16.h>
#include <math.h>
#include <stdint.h>

// Problem constants
#define NH 1024
#define NF 4096
#define NE 8
#define NG 9                  // 8 experts + shared fallback
#define NTOK 4096
#define CAPE 512
#define MT 128                // M tile
#define NTILE 128             // N tile
#define KC 32                 // K chunk per stage
#define NSTAGE 4
#define MAXTILES 64

// stage layout (bytes): Ahi | Alo | Bhi | Blo, each 128x32 bf16 = 8KB
#define A_HI 0
#define A_LO 8192
#define B_HI 16384
#define B_LO 24576
#define STAGE_BYTES 32768
#define SMEMSZ (1024 + NSTAGE*STAGE_BYTES)

typedef __nv_bfloat16 bf16;

// ---------------- static device scratch ----------------
__device__ __align__(16) bf16 g_xhi[(size_t)NTOK * NH];
__device__ __align__(16) bf16 g_xlo[(size_t)NTOK * NH];
__device__ __align__(16) bf16 g_w1hi[(size_t)NG * NF * NH]; // [g][n=F][k=H]
__device__ __align__(16) bf16 g_w1lo[(size_t)NG * NF * NH];
__device__ __align__(16) bf16 g_w2hi[(size_t)NG * NH * NF]; // [g][n=H][k=F]
__device__ __align__(16) bf16 g_w2lo[(size_t)NG * NH * NF];
__device__ __align__(16) bf16 g_hhi[(size_t)NTOK * NF];
__device__ __align__(16) bf16 g_hlo[(size_t)NTOK * NF];
__device__ int g_prim[NTOK];
__device__ int g_sec[NTOK];
__device__ int g_gather[NTOK];
__device__ int g_goff[NG + 1];
__device__ int g_ntiles;
__device__ int g_tile_group[MAXTILES];
__device__ int g_tile_row[MAXTILES];

// ---------------- helpers ----------------
__device__ __forceinline__ uint32_t smem_u32(const void* p) {
    uint32_t a;
    asm("{ .reg .u64 t; cvta.to.shared.u64 t, %1; cvt.u32.u64 %0, t; }" : "=r"(a) : "l"(p));
    return a;
}
__device__ __forceinline__ void cpasync16(uint32_t s, const void* g) {
    asm volatile("cp.async.cg.shared.global [%0], [%1], 16;" :: "r"(s), "l"(g) : "memory");
}
__device__ __forceinline__ void ldm4(uint32_t* r, uint32_t addr) {
    asm volatile("ldmatrix.sync.aligned.m8n8.x4.shared.b16 {%0,%1,%2,%3}, [%4];"
                 : "=r"(r[0]), "=r"(r[1]), "=r"(r[2]), "=r"(r[3]) : "r"(addr));
}
__device__ __forceinline__ void mma16816(float* d, const uint32_t* a, uint32_t b0, uint32_t b1) {
    asm volatile(
        "mma.sync.aligned.m16n8k16.row.col.f32.bf16.bf16.f32 "
        "{%0,%1,%2,%3}, {%4,%5,%6,%7}, {%8,%9}, {%0,%1,%2,%3};"
        : "+f"(d[0]), "+f"(d[1]), "+f"(d[2]), "+f"(d[3])
        : "r"(a[0]), "r"(a[1]), "r"(a[2]), "r"(a[3]), "r"(b0), "r"(b1));
}
// swizzled 16B-chunk offset within a stage buffer (64B rows, 4 chunks/row)
__device__ __forceinline__ uint32_t swoff(int row, int ch) {
    return (uint32_t)((row * 4 + (ch ^ (row & 3))) << 4);
}

// ---------------------------------------------------------------------------
// Router
// ---------------------------------------------------------------------------
__global__ __launch_bounds__(256) void router_kernel(
    const float* __restrict__ x, const float* __restrict__ rw,
    const float* __restrict__ rb)
{
    int n = blockIdx.x;
    __shared__ float s_log[NE];
    int wid = threadIdx.x >> 5, lane = threadIdx.x & 31;
    const float* xr = x + (size_t)n * NH;
    const float* wr = rw + (size_t)wid * NH;
    float s = 0.f;
    #pragma unroll 8
    for (int k = lane; k < NH; k += 32) s += xr[k] * wr[k];
    #pragma unroll
    for (int o = 16; o; o >>= 1) s += __shfl_xor_sync(0xffffffffu, s, o);
    if (lane == 0) s_log[wid] = s + rb[wid];
    __syncthreads();
    if (threadIdx.x == 0) {
        float b0 = -INFINITY; int i0 = 0;
        #pragma unroll
        for (int e = 0; e < NE; e++) { float v = s_log[e]; if (v > b0) { b0 = v; i0 = e; } }
        float b1 = -INFINITY; int i1 = 0;
        #pragma unroll
        for (int e = 0; e < NE; e++) { if (e == i0) continue; float v = s_log[e]; if (v > b1) { b1 = v; i1 = e; } }
        g_prim[n] = i0; g_sec[n] = i1;
    }
}

// ---------------------------------------------------------------------------
// Capacity assignment (exact reference semantics)
// ---------------------------------------------------------------------------
__global__ __launch_bounds__(320) void assign_kernel()
{
    __shared__ unsigned char s_prim[NTOK], s_sec[NTOK], s_keep[NTOK], s_assign[NTOK];
    __shared__ int s_used[NE], s_gcnt[NG], s_goff[NG + 1];
    int tid = threadIdx.x;
    int wid = tid >> 5, lane = tid & 31;
    unsigned lmask = (1u << lane) - 1u;

    for (int t = tid; t < NTOK; t += blockDim.x) {
        s_prim[t] = (unsigned char)g_prim[t];
        s_sec[t]  = (unsigned char)g_sec[t];
    }
    __syncthreads();

    if (wid < NE) {
        int e = wid, run = 0;
        for (int c = 0; c < NTOK; c += 32) {
            int t = c + lane;
            bool bit = (s_prim[t] == e);
            unsigned m = __ballot_sync(0xffffffffu, bit);
            if (bit) {
                int pos = run + __popc(m & lmask);
                bool keep = pos < CAPE;
                s_keep[t]   = keep ? 1 : 0;
                s_assign[t] = keep ? (unsigned char)e : (unsigned char)255;
            }
            run += __popc(m);
        }
        if (lane == 0) s_used[e] = run < CAPE ? run : CAPE;
    }
    __syncthreads();

    if (wid < NE) {
        int e = wid, run = 0, used = s_used[e];
        for (int c = 0; c < NTOK; c += 32) {
            int t = c + lane;
            bool bit = (s_sec[t] == e) && (s_keep[t] == 0);
            unsigned m = __ballot_sync(0xffffffffu, bit);
            if (bit) {
                int pos2 = run + __popc(m & lmask);
                bool take2 = (used + pos2) < CAPE;
                s_assign[t] = take2 ? (unsigned char)e : (unsigned char)8;
            }
            run += __popc(m);
        }
    }
    __syncthreads();

    if (wid < NG) {
        int g = wid, run = 0;
        for (int c = 0; c < NTOK; c += 32) {
            int t = c + lane;
            unsigned m = __ballot_sync(0xffffffffu, s_assign[t] == g);
            run += __popc(m);
        }
        if (lane == 0) s_gcnt[g] = run;
    }
    __syncthreads();

    if (tid == 0) {
        s_goff[0] = 0;
        for (int g = 0; g < NG; g++) s_goff[g + 1] = s_goff[g] + s_gcnt[g];
        int nt = 0;
        for (int g = 0; g < NG; g++)
            for (int r = s_goff[g]; r < s_goff[g + 1]; r += MT) {
                g_tile_group[nt] = g; g_tile_row[nt] = r; nt++;
            }
        g_ntiles = nt;
        for (int g = 0; g <= NG; g++) g_goff[g] = s_goff[g];
    }
    __syncthreads();

    if (wid < NG) {
        int g = wid, run = 0, base = s_goff[g];
        for (int c = 0; c < NTOK; c += 32) {
            int t = c + lane;
            bool bit = (s_assign[t] == g);
            unsigned m = __ballot_sync(0xffffffffu, bit);
            if (bit) g_gather[base + run + __popc(m & lmask)] = t;
            run += __popc(m);
        }
    }
}

// ---------------------------------------------------------------------------
// Convert + gather x into grouped bf16 hi/lo
// ---------------------------------------------------------------------------
__global__ __launch_bounds__(256) void convert_x_kernel(const float* __restrict__ x)
{
    int r = blockIdx.x;
    int tok = g_gather[r];
    const float* src = x + (size_t)tok * NH;
    bf16* dh = g_xhi + (size_t)r * NH;
    bf16* dl = g_xlo + (size_t)r * NH;
    for (int i = threadIdx.x; i < NH; i += 256) {
        float v = src[i];
        bf16 h = __float2bfloat16(v);
        dh[i] = h;
        dl[i] = __float2bfloat16(v - __bfloat162float(h));
    }
}

// ---------------------------------------------------------------------------
// Convert + transpose weights: W[g][k][n] (fp32) -> Out[g][n][k] (bf16 hi/lo)
// ---------------------------------------------------------------------------
template<int KD, int ND, bool W1SEL>
__global__ void convert_w_kernel(const float* __restrict__ Wexp, const float* __restrict__ Wfb)
{
    __shared__ float t[32][33];
    int g = blockIdx.z;
    const float* W = (g < NE) ? (Wexp + (size_t)g * KD * ND) : Wfb;
    bf16* Ohi = (W1SEL ? g_w1hi : g_w2hi) + (size_t)g * ND * KD;
    bf16* Olo = (W1SEL ? g_w1lo : g_w2lo) + (size_t)g * ND * KD;
    int kb = blockIdx.x * 32, nb = blockIdx.y * 32;
    int tx = threadIdx.x, ty = threadIdx.y;
    #pragma unroll
    for (int i = ty; i < 32; i += 8)
        t[i][tx] = W[(size_t)(kb + i) * ND + nb + tx];
    __syncthreads();
    #pragma unroll
    for (int j = ty; j < 32; j += 8) {
        float v = t[tx][j];
        bf16 h = __float2bfloat16(v);
        bf16 l = __float2bfloat16(v - __bfloat162float(h));
        size_t o = (size_t)(nb + j) * KD + kb + tx;
        Ohi[o] = h; Olo[o] = l;
    }
}

// ---------------------------------------------------------------------------
// Grouped GEMM on mma.sync bf16 (3-pass hi/lo split), 128x128 tile, 8 warps.
// FIRST: A=g_x*, B=g_w1* -> bias+gelu -> g_h hi/lo
// else : A=g_h*, B=g_w2* -> bias -> scatter fp32 to out
// ---------------------------------------------------------------------------
template<int KDIM, int NDIM, bool FIRST>
__global__ __launch_bounds__(256, 1) void moe_gemm_mma(
    const float* __restrict__ BiasE, const float* __restrict__ BiasF,
    float* __restrict__ Cout)
{
    constexpr int NCH = KDIM / KC;
    extern __shared__ __align__(1024) char smem[];

    int tileIdx = blockIdx.y;
    if (tileIdx >= g_ntiles) return;
    int tid = threadIdx.x, wid = tid >> 5, lane = tid & 31;
    int g    = g_tile_group[tileIdx];
    int row0 = g_tile_row[tileIdx];
    int rend = g_goff[g + 1];
    int n0   = blockIdx.x * NTILE;
    const float* bias = (g < NE) ? (BiasE + (size_t)g * NDIM) : BiasF;

    const bf16* Ahi = FIRST ? g_xhi : g_hhi;
    const bf16* Alo = FIRST ? g_xlo : g_hlo;
    const bf16* Bhi = FIRST ? g_w1hi : g_w2hi;
    const bf16* Blo = FIRST ? g_w1lo : g_w2lo;

    int*   s_rows = (int*)smem;            // 128 ints
    float* s_bias = (float*)(smem + 512);  // 128 floats
    uint32_t stage0 = smem_u32(smem) + 1024;

    if (tid < MT) {
        int r = row0 + tid;
        s_rows[tid] = (r < NTOK) ? g_gather[r] : 0;
        s_bias[tid] = bias[n0 + tid];
    }
    __syncthreads();

    auto load_stage = [&](int s, int c) {
        uint32_t st = stage0 + s * STAGE_BYTES;
        int k0 = c * KC;
        #pragma unroll
        for (int i = tid; i < 1024; i += 256) {          // A hi|lo: 512 chunks each
            int buf = i >> 9, idx = i & 511;
            int row = idx >> 2, ch = idx & 3;
            int gr = row0 + row; if (gr >= NTOK) gr = NTOK - 1;
            const bf16* src = (buf ? Alo : Ahi) + (size_t)gr * KDIM + k0 + ch * 8;
            cpasync16(st + (buf ? A_LO : A_HI) + swoff(row, ch), src);
        }
        #pragma unroll
        for (int i = tid; i < 1024; i += 256) {          // B hi|lo
            int buf = i >> 9, idx = i & 511;
            int row = idx >> 2, ch = idx & 3;
            const bf16* src = (buf ? Blo : Bhi) + ((size_t)g * NDIM + n0 + row) * KDIM + k0 + ch * 8;
            cpasync16(st + (buf ? B_LO : B_HI) + swoff(row, ch), src);
        }
        asm volatile("cp.async.commit_group;" ::: "memory");
    };

    load_stage(0, 0);
    load_stage(1, 1);
    load_stage(2, 2);

    int wm = (wid >> 2) * 64;   // warp M offset (2 warp-rows)
    int wn = (wid & 3) * 32;    // warp N offset (4 warp-cols)

    float d[4][4][4];
    #pragma unroll
    for (int a = 0; a < 4; a++)
        #pragma unroll
        for (int b = 0; b < 4; b++)
            #pragma unroll
            for (int c = 0; c < 4; c++) d[a][b][c] = 0.f;

    for (int c = 0; c < NCH; c++) {
        asm volatile("cp.async.wait_group 2;" ::: "memory");
        __syncthreads();
        if (c + 3 < NCH) load_stage((c + 3) & 3, c + 3);
        else asm volatile("cp.async.commit_group;" ::: "memory");

        uint32_t st = stage0 + (c & 3) * STAGE_BYTES;
        #pragma unroll
        for (int s = 0; s < 2; s++) {
            uint32_t ah[4][4], al[4][4], bh[2][4], bl[2][4];
            int ach = s * 2 + (lane >> 4);
            #pragma unroll
            for (int mt = 0; mt < 4; mt++) {
                int row = wm + mt * 16 + (lane & 15);
                uint32_t off = swoff(row, ach);
                ldm4(ah[mt], st + A_HI + off);
                ldm4(al[mt], st + A_LO + off);
            }
            #pragma unroll
            for (int nt = 0; nt < 2; nt++) {
                int row = wn + nt * 16 + (lane & 15);
                uint32_t off = swoff(row, ach);
                ldm4(bh[nt], st + B_HI + off);
                ldm4(bl[nt], st + B_LO + off);
            }
            #pragma unroll
            for (int mt = 0; mt < 4; mt++)
                #pragma unroll
                for (int j = 0; j < 4; j++) {
                    int nt = j >> 1, sl = j & 1;
                    mma16816(d[mt][j], ah[mt], bh[nt][sl], bh[nt][sl + 2]);
                    mma16816(d[mt][j], ah[mt], bl[nt][sl], bl[nt][sl + 2]);
                    mma16816(d[mt][j], al[mt], bh[nt][sl], bh[nt][sl + 2]);
                }
        }
    }

    // epilogue
    int r4 = lane >> 2, c2 = (lane & 3) * 2;
    #pragma unroll
    for (int mt = 0; mt < 4; mt++) {
        #pragma unroll
        for (int half = 0; half < 2; half++) {
            int lr = wm + mt * 16 + r4 + half * 8;
            int grow = row0 + lr;
            if (grow >= rend) continue;
            int tok = s_rows[lr];
            #pragma unroll
            for (int j = 0; j < 4; j++) {
                int col = wn + j * 8 + c2;
                float v0 = d[mt][j][half * 2 + 0] + s_bias[col];
                float v1 = d[mt][j][half * 2 + 1] + s_bias[col + 1];
                if (FIRST) {
                    v0 = 0.5f * v0 * (1.0f + erff(v0 * 0.70710678118654752440f));
                    v1 = 0.5f * v1 * (1.0f + erff(v1 * 0.70710678118654752440f));
                    bf16 h0 = __float2bfloat16(v0), h1 = __float2bfloat16(v1);
                    bf16 l0 = __float2bfloat16(v0 - __bfloat162float(h0));
                    bf16 l1 = __float2bfloat16(v1 - __bfloat162float(h1));
                    uint32_t hp = (uint32_t)__bfloat16_as_ushort(h0) | ((uint32_t)__bfloat16_as_ushort(h1) << 16);
                    uint32_t lp = (uint32_t)__bfloat16_as_ushort(l0) | ((uint32_t)__bfloat16_as_ushort(l1) << 16);
                    *(uint32_t*)(g_hhi + (size_t)grow * NDIM + n0 + col) = hp;
                    *(uint32_t*)(g_hlo + (size_t)grow * NDIM + n0 + col) = lp;
                } else {
                    float2 v = make_float2(v0, v1);
                    *(float2*)(Cout + (size_t)tok * NDIM + n0 + col) = v;
                }
            }
        }
    }
}

// ---------------------------------------------------------------------------
extern "C" void kernel_launch(void* const* d_in, const int* in_sizes, int n_in,
                              void* d_out, int out_size)
{
    const float* x   = (const float*)d_in[0];
    const float* rw  = (const float*)d_in[1];
    const float* rb  = (const float*)d_in[2];
    const float* w1  = (const float*)d_in[3];
    const float* b1  = (const float*)d_in[4];
    const float* w2  = (const float*)d_in[5];
    const float* b2  = (const float*)d_in[6];
    const float* sw1 = (const float*)d_in[7];
    const float* sb1 = (const float*)d_in[8];
    const float* sw2 = (const float*)d_in[9];
    const float* sb2 = (const float*)d_in[10];
    float* out = (float*)d_out;

    cudaFuncSetAttribute(moe_gemm_mma<NH, NF, true>,
                         cudaFuncAttributeMaxDynamicSharedMemorySize, SMEMSZ);
    cudaFuncSetAttribute(moe_gemm_mma<NF, NH, false>,
                         cudaFuncAttributeMaxDynamicSharedMemorySize, SMEMSZ);

    router_kernel<<<NTOK, 256>>>(x, rw, rb);
    assign_kernel<<<1, 320>>>();
    convert_x_kernel<<<NTOK, 256>>>(x);
    dim3 cb(32, 8);
    convert_w_kernel<NH, NF, true ><<<dim3(NH / 32, NF / 32, NG), cb>>>(w1, sw1);
    convert_w_kernel<NF, NH, false><<<dim3(NF / 32, NH / 32, NG), cb>>>(w2, sw2);
    // GEMM1: grouped x @ w1 -> gelu -> g_h (hi/lo)
    moe_gemm_mma<NH, NF, true ><<<dim3(NF / NTILE, 40), 256, SMEMSZ>>>(b1, sb1, nullptr);
    // GEMM2: g_h @ w2 -> scatter to out
    moe_gemm_mma<NF, NH, false><<<dim3(NH / NTILE, 40), 256, SMEMSZ>>>(b2, sb2, out);
}

// round 4
// speedup vs baseline: 2.4769x; 1.2535x over previous
#include <cuda_runtime.h>
#include <cuda_bf16.h>
#include <math.h>
#include <stdint.h>

// Problem constants
#define NH 1024
#define NF 4096
#define NE 8
#define NG 9                  // 8 experts + shared fallback
#define NTOK 4096
#define CAPE 512
#define MT 128                // M tile
#define NTILE 128             // N tile
#define KC 32                 // K chunk per stage
#define NSTAGE 4
#define MAXTILES 64

// stage layout (bytes): Ahi | Alo | Bhi | Blo, each 8KB
//   A: [128 m][32 k] bf16, row pitch 64B
//   B: [32 k][128 n] bf16, row pitch 256B
#define A_HI 0
#define A_LO 8192
#define B_HI 16384
#define B_LO 24576
#define STAGE_BYTES 32768
#define SMEMSZ (1024 + NSTAGE*STAGE_BYTES)

typedef __nv_bfloat16 bf16;

// ---------------- static device scratch ----------------
__device__ __align__(16) bf16 g_xhi[(size_t)NTOK * NH];   // [m][k]
__device__ __align__(16) bf16 g_xlo[(size_t)NTOK * NH];
__device__ __align__(16) bf16 g_w1hi[(size_t)NG * NH * NF]; // [g][k=H][n=F]  (native layout)
__device__ __align__(16) bf16 g_w1lo[(size_t)NG * NH * NF];
__device__ __align__(16) bf16 g_w2hi[(size_t)NG * NF * NH]; // [g][k=F][n=H]
__device__ __align__(16) bf16 g_w2lo[(size_t)NG * NF * NH];
__device__ __align__(16) bf16 g_hhi[(size_t)NTOK * NF];   // [m][k] grouped
__device__ __align__(16) bf16 g_hlo[(size_t)NTOK * NF];
__device__ int g_prim[NTOK];
__device__ int g_sec[NTOK];
__device__ int g_gather[NTOK];
__device__ int g_goff[NG + 1];
__device__ int g_ntiles;
__device__ int g_tile_group[MAXTILES];
__device__ int g_tile_row[MAXTILES];

// ---------------- helpers ----------------
__device__ __forceinline__ uint32_t smem_u32(const void* p) {
    uint32_t a;
    asm("{ .reg .u64 t; cvta.to.shared.u64 t, %1; cvt.u32.u64 %0, t; }" : "=r"(a) : "l"(p));
    return a;
}
__device__ __forceinline__ void cpasync16(uint32_t s, const void* g) {
    asm volatile("cp.async.cg.shared.global [%0], [%1], 16;" :: "r"(s), "l"(g) : "memory");
}
__device__ __forceinline__ void ldm4(uint32_t* r, uint32_t addr) {
    asm volatile("ldmatrix.sync.aligned.m8n8.x4.shared.b16 {%0,%1,%2,%3}, [%4];"
                 : "=r"(r[0]), "=r"(r[1]), "=r"(r[2]), "=r"(r[3]) : "r"(addr));
}
__device__ __forceinline__ void ldm4t(uint32_t* r, uint32_t addr) {
    asm volatile("ldmatrix.sync.aligned.m8n8.x4.trans.shared.b16 {%0,%1,%2,%3}, [%4];"
                 : "=r"(r[0]), "=r"(r[1]), "=r"(r[2]), "=r"(r[3]) : "r"(addr));
}
__device__ __forceinline__ void mma16816(float* d, const uint32_t* a, uint32_t b0, uint32_t b1) {
    asm volatile(
        "mma.sync.aligned.m16n8k16.row.col.f32.bf16.bf16.f32 "
        "{%0,%1,%2,%3}, {%4,%5,%6,%7}, {%8,%9}, {%0,%1,%2,%3};"
        : "+f"(d[0]), "+f"(d[1]), "+f"(d[2]), "+f"(d[3])
        : "r"(a[0]), "r"(a[1]), "r"(a[2]), "r"(a[3]), "r"(b0), "r"(b1));
}
// A-tile swizzle: 64B rows, 4 x 16B chunks/row
__device__ __forceinline__ uint32_t swA(int row, int ch) {
    return (uint32_t)((row * 4 + (ch ^ (row & 3))) << 4);
}
// B-tile swizzle: 256B rows, 16 x 16B chunks/row
__device__ __forceinline__ uint32_t swB(int krow, int ch) {
    return (uint32_t)((krow * 16 + (ch ^ (krow & 7))) << 4);
}

// ---------------------------------------------------------------------------
// Router
// ---------------------------------------------------------------------------
__global__ __launch_bounds__(256) void router_kernel(
    const float* __restrict__ x, const float* __restrict__ rw,
    const float* __restrict__ rb)
{
    int n = blockIdx.x;
    __shared__ float s_log[NE];
    int wid = threadIdx.x >> 5, lane = threadIdx.x & 31;
    const float* xr = x + (size_t)n * NH;
    const float* wr = rw + (size_t)wid * NH;
    float s = 0.f;
    #pragma unroll 8
    for (int k = lane; k < NH; k += 32) s += xr[k] * wr[k];
    #pragma unroll
    for (int o = 16; o; o >>= 1) s += __shfl_xor_sync(0xffffffffu, s, o);
    if (lane == 0) s_log[wid] = s + rb[wid];
    __syncthreads();
    if (threadIdx.x == 0) {
        float b0 = -INFINITY; int i0 = 0;
        #pragma unroll
        for (int e = 0; e < NE; e++) { float v = s_log[e]; if (v > b0) { b0 = v; i0 = e; } }
        float b1 = -INFINITY; int i1 = 0;
        #pragma unroll
        for (int e = 0; e < NE; e++) { if (e == i0) continue; float v = s_log[e]; if (v > b1) { b1 = v; i1 = e; } }
        g_prim[n] = i0; g_sec[n] = i1;
    }
}

// ---------------------------------------------------------------------------
// Capacity assignment (exact reference semantics)
// ---------------------------------------------------------------------------
__global__ __launch_bounds__(320) void assign_kernel()
{
    __shared__ unsigned char s_prim[NTOK], s_sec[NTOK], s_keep[NTOK], s_assign[NTOK];
    __shared__ int s_used[NE], s_gcnt[NG], s_goff[NG + 1];
    int tid = threadIdx.x;
    int wid = tid >> 5, lane = tid & 31;
    unsigned lmask = (1u << lane) - 1u;

    for (int t = tid; t < NTOK; t += blockDim.x) {
        s_prim[t] = (unsigned char)g_prim[t];
        s_sec[t]  = (unsigned char)g_sec[t];
    }
    __syncthreads();

    if (wid < NE) {
        int e = wid, run = 0;
        for (int c = 0; c < NTOK; c += 32) {
            int t = c + lane;
            bool bit = (s_prim[t] == e);
            unsigned m = __ballot_sync(0xffffffffu, bit);
            if (bit) {
                int pos = run + __popc(m & lmask);
                bool keep = pos < CAPE;
                s_keep[t]   = keep ? 1 : 0;
                s_assign[t] = keep ? (unsigned char)e : (unsigned char)255;
            }
            run += __popc(m);
        }
        if (lane == 0) s_used[e] = run < CAPE ? run : CAPE;
    }
    __syncthreads();

    if (wid < NE) {
        int e = wid, run = 0, used = s_used[e];
        for (int c = 0; c < NTOK; c += 32) {
            int t = c + lane;
            bool bit = (s_sec[t] == e) && (s_keep[t] == 0);
            unsigned m = __ballot_sync(0xffffffffu, bit);
            if (bit) {
                int pos2 = run + __popc(m & lmask);
                bool take2 = (used + pos2) < CAPE;
                s_assign[t] = take2 ? (unsigned char)e : (unsigned char)8;
            }
            run += __popc(m);
        }
    }
    __syncthreads();

    if (wid < NG) {
        int g = wid, run = 0;
        for (int c = 0; c < NTOK; c += 32) {
            int t = c + lane;
            unsigned m = __ballot_sync(0xffffffffu, s_assign[t] == g);
            run += __popc(m);
        }
        if (lane == 0) s_gcnt[g] = run;
    }
    __syncthreads();

    if (tid == 0) {
        s_goff[0] = 0;
        for (int g = 0; g < NG; g++) s_goff[g + 1] = s_goff[g] + s_gcnt[g];
        int nt = 0;
        for (int g = 0; g < NG; g++)
            for (int r = s_goff[g]; r < s_goff[g + 1]; r += MT) {
                g_tile_group[nt] = g; g_tile_row[nt] = r; nt++;
            }
        g_ntiles = nt;
        for (int g = 0; g <= NG; g++) g_goff[g] = s_goff[g];
    }
    __syncthreads();

    if (wid < NG) {
        int g = wid, run = 0, base = s_goff[g];
        for (int c = 0; c < NTOK; c += 32) {
            int t = c + lane;
            bool bit = (s_assign[t] == g);
            unsigned m = __ballot_sync(0xffffffffu, bit);
            if (bit) g_gather[base + run + __popc(m & lmask)] = t;
            run += __popc(m);
        }
    }
}

// ---------------------------------------------------------------------------
// Convert + gather x into grouped bf16 hi/lo (vectorized)
// ---------------------------------------------------------------------------
__global__ __launch_bounds__(256) void convert_x_kernel(const float* __restrict__ x)
{
    int r = blockIdx.x;
    int tok = g_gather[r];
    const float4* src = (const float4*)(x + (size_t)tok * NH);
    int i = threadIdx.x;                 // NH/4 = 256 float4 per row
    float4 v = src[i];
    bf16 h0 = __float2bfloat16(v.x), h1 = __float2bfloat16(v.y);
    bf16 h2 = __float2bfloat16(v.z), h3 = __float2bfloat16(v.w);
    bf16 l0 = __float2bfloat16(v.x - __bfloat162float(h0));
    bf16 l1 = __float2bfloat16(v.y - __bfloat162float(h1));
    bf16 l2 = __float2bfloat16(v.z - __bfloat162float(h2));
    bf16 l3 = __float2bfloat16(v.w - __bfloat162float(h3));
    uint2 hp, lp;
    hp.x = (uint32_t)__bfloat16_as_ushort(h0) | ((uint32_t)__bfloat16_as_ushort(h1) << 16);
    hp.y = (uint32_t)__bfloat16_as_ushort(h2) | ((uint32_t)__bfloat16_as_ushort(h3) << 16);
    lp.x = (uint32_t)__bfloat16_as_ushort(l0) | ((uint32_t)__bfloat16_as_ushort(l1) << 16);
    lp.y = (uint32_t)__bfloat16_as_ushort(l2) | ((uint32_t)__bfloat16_as_ushort(l3) << 16);
    ((uint2*)(g_xhi + (size_t)r * NH))[i] = hp;
    ((uint2*)(g_xlo + (size_t)r * NH))[i] = lp;
}

// ---------------------------------------------------------------------------
// Streaming weight conversion, NO transpose: W[g][k][n] fp32 -> hi/lo bf16 same layout
// ---------------------------------------------------------------------------
template<bool W1SEL>
__global__ __launch_bounds__(256) void convert_w_kernel(
    const float* __restrict__ Wexp, const float* __restrict__ Wfb)
{
    const size_t perg = (size_t)NH * NF;
    int g = blockIdx.z;
    const float4* src = (const float4*)((g < NE) ? (Wexp + (size_t)g * perg) : Wfb);
    uint2* dh = (uint2*)((W1SEL ? g_w1hi : g_w2hi) + (size_t)g * perg);
    uint2* dl = (uint2*)((W1SEL ? g_w1lo : g_w2lo) + (size_t)g * perg);
    size_t n4 = perg / 4;
    for (size_t i = blockIdx.x * 256 + threadIdx.x; i < n4; i += (size_t)gridDim.x * 256) {
        float4 v = src[i];
        bf16 h0 = __float2bfloat16(v.x), h1 = __float2bfloat16(v.y);
        bf16 h2 = __float2bfloat16(v.z), h3 = __float2bfloat16(v.w);
        bf16 l0 = __float2bfloat16(v.x - __bfloat162float(h0));
        bf16 l1 = __float2bfloat16(v.y - __bfloat162float(h1));
        bf16 l2 = __float2bfloat16(v.z - __bfloat162float(h2));
        bf16 l3 = __float2bfloat16(v.w - __bfloat162float(h3));
        uint2 hp, lp;
        hp.x = (uint32_t)__bfloat16_as_ushort(h0) | ((uint32_t)__bfloat16_as_ushort(h1) << 16);
        hp.y = (uint32_t)__bfloat16_as_ushort(h2) | ((uint32_t)__bfloat16_as_ushort(h3) << 16);
        lp.x = (uint32_t)__bfloat16_as_ushort(l0) | ((uint32_t)__bfloat16_as_ushort(l1) << 16);
        lp.y = (uint32_t)__bfloat16_as_ushort(l2) | ((uint32_t)__bfloat16_as_ushort(l3) << 16);
        dh[i] = hp; dl[i] = lp;
    }
}

// ---------------------------------------------------------------------------
// Grouped GEMM on mma.sync bf16 (3-pass hi/lo split), 128x128 tile, 8 warps.
// A: [m][k] gathered grouped rows (non-trans ldmatrix)
// B: global [k][n], smem [k][n], ldmatrix.trans
// ---------------------------------------------------------------------------
struct Frags { uint32_t ah[4][4], al[4][4], bh[2][4], bl[2][4]; };

template<int KDIM, int NDIM, bool FIRST>
__global__ __launch_bounds__(256, 1) void moe_gemm_mma(
    const float* __restrict__ BiasE, const float* __restrict__ BiasF,
    float* __restrict__ Cout)
{
    constexpr int NCH = KDIM / KC;
    extern __shared__ __align__(1024) char smem[];

    int tileIdx = blockIdx.y;
    if (tileIdx >= g_ntiles) return;
    int tid = threadIdx.x, wid = tid >> 5, lane = tid & 31;
    int g    = g_tile_group[tileIdx];
    int row0 = g_tile_row[tileIdx];
    int rend = g_goff[g + 1];
    int n0   = blockIdx.x * NTILE;
    const float* bias = (g < NE) ? (BiasE + (size_t)g * NDIM) : BiasF;

    const bf16* Ahi = FIRST ? g_xhi : g_hhi;
    const bf16* Alo = FIRST ? g_xlo : g_hlo;
    const bf16* Bhi = (FIRST ? g_w1hi : g_w2hi) + (size_t)g * KDIM * NDIM;
    const bf16* Blo = (FIRST ? g_w1lo : g_w2lo) + (size_t)g * KDIM * NDIM;

    int*   s_rows = (int*)smem;            // 128 ints
    float* s_bias = (float*)(smem + 512);  // 128 floats
    uint32_t stage0 = smem_u32(smem) + 1024;

    if (tid < MT) {
        int r = row0 + tid;
        s_rows[tid] = (r < NTOK) ? g_gather[r] : 0;
        s_bias[tid] = bias[n0 + tid];
    }
    __syncthreads();

    auto load_stage = [&](int s, int c) {
        uint32_t st = stage0 + s * STAGE_BYTES;
        int k0 = c * KC;
        #pragma unroll
        for (int i = tid; i < 1024; i += 256) {          // A hi|lo: 512 chunks each
            int buf = i >> 9, idx = i & 511;
            int row = idx >> 2, ch = idx & 3;
            int gr = row0 + row; if (gr >= NTOK) gr = NTOK - 1;
            const bf16* src = (buf ? Alo : Ahi) + (size_t)gr * KDIM + k0 + ch * 8;
            cpasync16(st + (buf ? A_LO : A_HI) + swA(row, ch), src);
        }
        #pragma unroll
        for (int i = tid; i < 1024; i += 256) {          // B hi|lo: [32 k][128 n]
            int buf = i >> 9, idx = i & 511;
            int kr = idx >> 4, ch = idx & 15;
            const bf16* src = (buf ? Blo : Bhi) + (size_t)(k0 + kr) * NDIM + n0 + ch * 8;
            cpasync16(st + (buf ? B_LO : B_HI) + swB(kr, ch), src);
        }
        asm volatile("cp.async.commit_group;" ::: "memory");
    };

    load_stage(0, 0);
    load_stage(1, 1);
    load_stage(2, 2);

    int wm = (wid >> 2) * 64;   // warp M offset
    int wn = (wid & 3) * 32;    // warp N offset

    // B ldmatrix.trans lane addressing (within the warp)
    int grp = lane >> 3, rit = lane & 7;
    int b_kadd = (grp & 1) * 8 + rit;      // k row within k16
    int b_nsub = (grp >> 1) * 8;           // n sub-offset

    float d[4][4][4];
    #pragma unroll
    for (int a = 0; a < 4; a++)
        #pragma unroll
        for (int b = 0; b < 4; b++)
            #pragma unroll
            for (int c = 0; c < 4; c++) d[a][b][c] = 0.f;

    Frags F[2];

    auto load_frags = [&](int s, uint32_t st, Frags& f) {
        int ach = s * 2 + (lane >> 4);
        #pragma unroll
        for (int mt = 0; mt < 4; mt++) {
            int row = wm + mt * 16 + (lane & 15);
            uint32_t off = swA(row, ach);
            ldm4(f.ah[mt], st + A_HI + off);
            ldm4(f.al[mt], st + A_LO + off);
        }
        #pragma unroll
        for (int nt = 0; nt < 2; nt++) {
            int kl = s * 16 + b_kadd;
            int nch = (wn + nt * 16 + b_nsub) >> 3;
            uint32_t off = swB(kl, nch);
            ldm4t(f.bh[nt], st + B_HI + off);
            ldm4t(f.bl[nt], st + B_LO + off);
        }
    };

    auto do_mma = [&](Frags& f) {
        #pragma unroll
        for (int mt = 0; mt < 4; mt++)
            #pragma unroll
            for (int j = 0; j < 4; j++) {
                int nt = j >> 1, sl = j & 1;
                mma16816(d[mt][j], f.ah[mt], f.bh[nt][sl * 2], f.bh[nt][sl * 2 + 1]);
                mma16816(d[mt][j], f.ah[mt], f.bl[nt][sl * 2], f.bl[nt][sl * 2 + 1]);
                mma16816(d[mt][j], f.al[mt], f.bh[nt][sl * 2], f.bh[nt][sl * 2 + 1]);
            }
    };

    for (int c = 0; c < NCH; c++) {
        asm volatile("cp.async.wait_group 2;" ::: "memory");
        __syncthreads();
        if (c + 3 < NCH) load_stage((c + 3) & 3, c + 3);
        else asm volatile("cp.async.commit_group;" ::: "memory");

        uint32_t st = stage0 + (c & 3) * STAGE_BYTES;
        load_frags(0, st, F[0]);
        load_frags(1, st, F[1]);
        do_mma(F[0]);
        do_mma(F[1]);
    }

    // epilogue
    int r4 = lane >> 2, c2 = (lane & 3) * 2;
    #pragma unroll
    for (int mt = 0; mt < 4; mt++) {
        #pragma unroll
        for (int half = 0; half < 2; half++) {
            int lr = wm + mt * 16 + r4 + half * 8;
            int grow = row0 + lr;
            if (grow >= rend) continue;
            int tok = s_rows[lr];
            #pragma unroll
            for (int j = 0; j < 4; j++) {
                int col = wn + j * 8 + c2;
                float v0 = d[mt][j][half * 2 + 0] + s_bias[col];
                float v1 = d[mt][j][half * 2 + 1] + s_bias[col + 1];
                if (FIRST) {
                    v0 = 0.5f * v0 * (1.0f + erff(v0 * 0.70710678118654752440f));
                    v1 = 0.5f * v1 * (1.0f + erff(v1 * 0.70710678118654752440f));
                    bf16 h0 = __float2bfloat16(v0), h1 = __float2bfloat16(v1);
                    bf16 l0 = __float2bfloat16(v0 - __bfloat162float(h0));
                    bf16 l1 = __float2bfloat16(v1 - __bfloat162float(h1));
                    uint32_t hp = (uint32_t)__bfloat16_as_ushort(h0) | ((uint32_t)__bfloat16_as_ushort(h1) << 16);
                    uint32_t lp = (uint32_t)__bfloat16_as_ushort(l0) | ((uint32_t)__bfloat16_as_ushort(l1) << 16);
                    *(uint32_t*)(g_hhi + (size_t)grow * NDIM + n0 + col) = hp;
                    *(uint32_t*)(g_hlo + (size_t)grow * NDIM + n0 + col) = lp;
                } else {
                    float2 v = make_float2(v0, v1);
                    *(float2*)(Cout + (size_t)tok * NDIM + n0 + col) = v;
                }
            }
        }
    }
}

// ---------------------------------------------------------------------------
extern "C" void kernel_launch(void* const* d_in, const int* in_sizes, int n_in,
                              void* d_out, int out_size)
{
    const float* x   = (const float*)d_in[0];
    const float* rw  = (const float*)d_in[1];
    const float* rb  = (const float*)d_in[2];
    const float* w1  = (const float*)d_in[3];
    const float* b1  = (const float*)d_in[4];
    const float* w2  = (const float*)d_in[5];
    const float* b2  = (const float*)d_in[6];
    const float* sw1 = (const float*)d_in[7];
    const float* sb1 = (const float*)d_in[8];
    const float* sw2 = (const float*)d_in[9];
    const float* sb2 = (const float*)d_in[10];
    float* out = (float*)d_out;

    cudaFuncSetAttribute(moe_gemm_mma<NH, NF, true>,
                         cudaFuncAttributeMaxDynamicSharedMemorySize, SMEMSZ);
    cudaFuncSetAttribute(moe_gemm_mma<NF, NH, false>,
                         cudaFuncAttributeMaxDynamicSharedMemorySize, SMEMSZ);

    router_kernel<<<NTOK, 256>>>(x, rw, rb);
    assign_kernel<<<1, 320>>>();
    convert_x_kernel<<<NTOK, 256>>>(x);
    convert_w_kernel<true ><<<dim3(512, 1, NG), 256>>>(w1, sw1);
    convert_w_kernel<false><<<dim3(512, 1, NG), 256>>>(w2, sw2);
    // GEMM1: grouped x @ w1 -> gelu -> g_h (hi/lo)
    moe_gemm_mma<NH, NF, true ><<<dim3(NF / NTILE, 40), 256, SMEMSZ>>>(b1, sb1, nullptr);
    // GEMM2: g_h @ w2 -> scatter to out
    moe_gemm_mma<NF, NH, false><<<dim3(NH / NTILE, 40), 256, SMEMSZ>>>(b2, sb2, out);
}

// round 7
// speedup vs baseline: 2.8170x; 1.1373x over previous
#include <cuda_runtime.h>
#include <cuda_bf16.h>
#include <math.h>
#include <stdint.h>

// Problem constants
#define NH 1024
#define NF 4096
#define NE 8
#define NG 9                  // 8 experts + shared fallback
#define NTOK 4096
#define CAPE 512
#define MT 128                // M tile
#define NTILE 128             // N tile
#define KC 32                 // K chunk per stage
#define NSTAGE 3
#define MAXTILES 64

// stage layout (bytes): Ahi | Alo | Bhi | Blo, each 8KB
//   A: [128 m][32 k] bf16, row pitch 64B
//   B: [32 k][128 n] bf16, row pitch 256B
#define A_HI 0
#define A_LO 8192
#define B_HI 16384
#define B_LO 24576
#define STAGE_BYTES 32768
#define SMEMSZ (1024 + NSTAGE*STAGE_BYTES)

typedef __nv_bfloat16 bf16;

// ---------------- static device scratch ----------------
__device__ __align__(16) bf16 g_xhi[(size_t)NTOK * NH];   // [token][k]
__device__ __align__(16) bf16 g_xlo[(size_t)NTOK * NH];
__device__ __align__(16) bf16 g_w1hi[(size_t)NG * NH * NF]; // [g][k=H][n=F]
__device__ __align__(16) bf16 g_w1lo[(size_t)NG * NH * NF];
__device__ __align__(16) bf16 g_w2hi[(size_t)NG * NF * NH]; // [g][k=F][n=H]
__device__ __align__(16) bf16 g_w2lo[(size_t)NG * NF * NH];
__device__ __align__(16) bf16 g_hhi[(size_t)NTOK * NF];   // [grouped row][k]
__device__ __align__(16) bf16 g_hlo[(size_t)NTOK * NF];
__device__ int g_prim[NTOK];
__device__ int g_sec[NTOK];
__device__ int g_gather[NTOK];
__device__ int g_goff[NG + 1];
__device__ int g_ntiles;
__device__ int g_tile_group[MAXTILES];
__device__ int g_tile_row[MAXTILES];

// ---------------- helpers ----------------
__device__ __forceinline__ uint32_t smem_u32(const void* p) {
    uint32_t a;
    asm("{ .reg .u64 t; cvta.to.shared.u64 t, %1; cvt.u32.u64 %0, t; }" : "=r"(a) : "l"(p));
    return a;
}
__device__ __forceinline__ void cpasync16(uint32_t s, const void* g) {
    asm volatile("cp.async.cg.shared.global [%0], [%1], 16;" :: "r"(s), "l"(g) : "memory");
}
__device__ __forceinline__ void ldm4(uint32_t* r, uint32_t addr) {
    asm volatile("ldmatrix.sync.aligned.m8n8.x4.shared.b16 {%0,%1,%2,%3}, [%4];"
                 : "=r"(r[0]), "=r"(r[1]), "=r"(r[2]), "=r"(r[3]) : "r"(addr));
}
__device__ __forceinline__ void ldm4t(uint32_t* r, uint32_t addr) {
    asm volatile("ldmatrix.sync.aligned.m8n8.x4.trans.shared.b16 {%0,%1,%2,%3}, [%4];"
                 : "=r"(r[0]), "=r"(r[1]), "=r"(r[2]), "=r"(r[3]) : "r"(addr));
}
__device__ __forceinline__ void mma16816(float* d, const uint32_t* a, uint32_t b0, uint32_t b1) {
    asm volatile(
        "mma.sync.aligned.m16n8k16.row.col.f32.bf16.bf16.f32 "
        "{%0,%1,%2,%3}, {%4,%5,%6,%7}, {%8,%9}, {%0,%1,%2,%3};"
        : "+f"(d[0]), "+f"(d[1]), "+f"(d[2]), "+f"(d[3])
        : "r"(a[0]), "r"(a[1]), "r"(a[2]), "r"(a[3]), "r"(b0), "r"(b1));
}
// A-tile swizzle: 64B rows, 4 x 16B chunks/row
__device__ __forceinline__ uint32_t swA(int row, int ch) {
    return (uint32_t)((row * 4 + (ch ^ (row & 3))) << 4);
}
// B-tile swizzle: 256B rows, 16 x 16B chunks/row
__device__ __forceinline__ uint32_t swB(int krow, int ch) {
    return (uint32_t)((krow * 16 + (ch ^ (krow & 7))) << 4);
}
__device__ __forceinline__ void split2(float v, bf16& h, bf16& l) {
    h = __float2bfloat16(v);
    l = __float2bfloat16(v - __bfloat162float(h));
}
__device__ __forceinline__ uint32_t pack2(bf16 a, bf16 b) {
    return (uint32_t)__bfloat16_as_ushort(a) | ((uint32_t)__bfloat16_as_ushort(b) << 16);
}

// ---------------------------------------------------------------------------
// Router + x split conversion fused (x hi/lo stored in TOKEN order)
// ---------------------------------------------------------------------------
__global__ __launch_bounds__(256) void router_kernel(
    const float* __restrict__ x, const float* __restrict__ rw,
    const float* __restrict__ rb)
{
    int n = blockIdx.x;
    __shared__ float s_log[NE];
    int tid = threadIdx.x;
    int wid = tid >> 5, lane = tid & 31;
    const float* xr = x + (size_t)n * NH;

    // conversion: 256 threads x 1 float4
    {
        float4 v = ((const float4*)xr)[tid];
        bf16 h0, h1, h2, h3, l0, l1, l2, l3;
        split2(v.x, h0, l0); split2(v.y, h1, l1);
        split2(v.z, h2, l2); split2(v.w, h3, l3);
        uint2 hp = make_uint2(pack2(h0, h1), pack2(h2, h3));
        uint2 lp = make_uint2(pack2(l0, l1), pack2(l2, l3));
        ((uint2*)(g_xhi + (size_t)n * NH))[tid] = hp;
        ((uint2*)(g_xlo + (size_t)n * NH))[tid] = lp;
    }

    const float* wr = rw + (size_t)wid * NH;
    float s = 0.f;
    #pragma unroll 8
    for (int k = lane; k < NH; k += 32) s += xr[k] * wr[k];
    #pragma unroll
    for (int o = 16; o; o >>= 1) s += __shfl_xor_sync(0xffffffffu, s, o);
    if (lane == 0) s_log[wid] = s + rb[wid];
    __syncthreads();
    if (tid == 0) {
        float b0 = -INFINITY; int i0 = 0;
        #pragma unroll
        for (int e = 0; e < NE; e++) { float v = s_log[e]; if (v > b0) { b0 = v; i0 = e; } }
        float b1 = -INFINITY; int i1 = 0;
        #pragma unroll
        for (int e = 0; e < NE; e++) { if (e == i0) continue; float v = s_log[e]; if (v > b1) { b1 = v; i1 = e; } }
        g_prim[n] = i0; g_sec[n] = i1;
    }
}

// ---------------------------------------------------------------------------
// Capacity assignment (exact reference semantics)
// ---------------------------------------------------------------------------
__global__ __launch_bounds__(320) void assign_kernel()
{
    __shared__ unsigned char s_prim[NTOK], s_sec[NTOK], s_keep[NTOK], s_assign[NTOK];
    __shared__ int s_used[NE], s_gcnt[NG], s_goff[NG + 1];
    int tid = threadIdx.x;
    int wid = tid >> 5, lane = tid & 31;
    unsigned lmask = (1u << lane) - 1u;

    for (int t = tid; t < NTOK; t += blockDim.x) {
        s_prim[t] = (unsigned char)g_prim[t];
        s_sec[t]  = (unsigned char)g_sec[t];
    }
    __syncthreads();

    if (wid < NE) {
        int e = wid, run = 0;
        for (int c = 0; c < NTOK; c += 32) {
            int t = c + lane;
            bool bit = (s_prim[t] == e);
            unsigned m = __ballot_sync(0xffffffffu, bit);
            if (bit) {
                int pos = run + __popc(m & lmask);
                bool keep = pos < CAPE;
                s_keep[t]   = keep ? 1 : 0;
                s_assign[t] = keep ? (unsigned char)e : (unsigned char)255;
            }
            run += __popc(m);
        }
        if (lane == 0) s_used[e] = run < CAPE ? run : CAPE;
    }
    __syncthreads();

    if (wid < NE) {
        int e = wid, run = 0, used = s_used[e];
        for (int c = 0; c < NTOK; c += 32) {
            int t = c + lane;
            bool bit = (s_sec[t] == e) && (s_keep[t] == 0);
            unsigned m = __ballot_sync(0xffffffffu, bit);
            if (bit) {
                int pos2 = run + __popc(m & lmask);
                bool take2 = (used + pos2) < CAPE;
                s_assign[t] = take2 ? (unsigned char)e : (unsigned char)8;
            }
            run += __popc(m);
        }
    }
    __syncthreads();

    if (wid < NG) {
        int g = wid, run = 0;
        for (int c = 0; c < NTOK; c += 32) {
            int t = c + lane;
            unsigned m = __ballot_sync(0xffffffffu, s_assign[t] == g);
            run += __popc(m);
        }
        if (lane == 0) s_gcnt[g] = run;
    }
    __syncthreads();

    if (tid == 0) {
        s_goff[0] = 0;
        for (int g = 0; g < NG; g++) s_goff[g + 1] = s_goff[g] + s_gcnt[g];
        int nt = 0;
        for (int g = 0; g < NG; g++)
            for (int r = s_goff[g]; r < s_goff[g + 1]; r += MT) {
                g_tile_group[nt] = g; g_tile_row[nt] = r; nt++;
            }
        g_ntiles = nt;
        for (int g = 0; g <= NG; g++) g_goff[g] = s_goff[g];
    }
    __syncthreads();

    if (wid < NG) {
        int g = wid, run = 0, base = s_goff[g];
        for (int c = 0; c < NTOK; c += 32) {
            int t = c + lane;
            bool bit = (s_assign[t] == g);
            unsigned m = __ballot_sync(0xffffffffu, bit);
            if (bit) g_gather[base + run + __popc(m & lmask)] = t;
            run += __popc(m);
        }
    }
}

// ---------------------------------------------------------------------------
// Streaming weight conversion (both w1 and w2 in one launch; blockIdx.y selects)
// ---------------------------------------------------------------------------
__global__ __launch_bounds__(256) void convert_w_kernel(
    const float* __restrict__ W1e, const float* __restrict__ W1f,
    const float* __restrict__ W2e, const float* __restrict__ W2f)
{
    const size_t perg = (size_t)NH * NF;
    int g = blockIdx.z;
    bool w1sel = (blockIdx.y == 0);
    const float* We = w1sel ? W1e : W2e;
    const float* Wf = w1sel ? W1f : W2f;
    const float4* src = (const float4*)((g < NE) ? (We + (size_t)g * perg) : Wf);
    uint2* dh = (uint2*)((w1sel ? g_w1hi : g_w2hi) + (size_t)g * perg);
    uint2* dl = (uint2*)((w1sel ? g_w1lo : g_w2lo) + (size_t)g * perg);
    size_t n4 = perg / 4;
    for (size_t i = blockIdx.x * 256 + threadIdx.x; i < n4; i += (size_t)gridDim.x * 256) {
        float4 v = src[i];
        bf16 h0, h1, h2, h3, l0, l1, l2, l3;
        split2(v.x, h0, l0); split2(v.y, h1, l1);
        split2(v.z, h2, l2); split2(v.w, h3, l3);
        dh[i] = make_uint2(pack2(h0, h1), pack2(h2, h3));
        dl[i] = make_uint2(pack2(l0, l1), pack2(l2, l3));
    }
}

// ---------------------------------------------------------------------------
// Grouped GEMM on mma.sync bf16 (3-pass hi/lo split), 128x128 tile, 8 warps,
// 3-stage cp.async pipeline, 2 CTAs/SM.
// A (FIRST): token-order g_x* gathered via s_rows; A (!FIRST): grouped g_h*.
// B: [k][n] smem, ldmatrix.trans.
// ---------------------------------------------------------------------------
template<int KDIM, int NDIM, bool FIRST>
__global__ __launch_bounds__(256, 2) void moe_gemm_mma(
    const float* __restrict__ BiasE, const float* __restrict__ BiasF,
    float* __restrict__ Cout)
{
    constexpr int NCH = KDIM / KC;
    extern __shared__ __align__(1024) char smem[];

    int tileIdx = blockIdx.y;
    if (tileIdx >= g_ntiles) return;
    int tid = threadIdx.x, wid = tid >> 5, lane = tid & 31;
    int g    = g_tile_group[tileIdx];
    int row0 = g_tile_row[tileIdx];
    int rend = g_goff[g + 1];
    int n0   = blockIdx.x * NTILE;
    const float* bias = (g < NE) ? (BiasE + (size_t)g * NDIM) : BiasF;

    const bf16* Ahi = FIRST ? g_xhi : g_hhi;
    const bf16* Alo = FIRST ? g_xlo : g_hlo;
    const bf16* Bhi = (FIRST ? g_w1hi : g_w2hi) + (size_t)g * KDIM * NDIM;
    const bf16* Blo = (FIRST ? g_w1lo : g_w2lo) + (size_t)g * KDIM * NDIM;

    int*   s_rows = (int*)smem;            // 128 ints
    float* s_bias = (float*)(smem + 512);  // 128 floats
    uint32_t stage0 = smem_u32(smem) + 1024;

    if (tid < MT) {
        int r = row0 + tid;
        s_rows[tid] = (r < NTOK) ? g_gather[r] : 0;
        s_bias[tid] = bias[n0 + tid];
    }
    __syncthreads();

    auto load_stage = [&](int s, int c) {
        uint32_t st = stage0 + s * STAGE_BYTES;
        int k0 = c * KC;
        #pragma unroll
        for (int i = tid; i < 1024; i += 256) {          // A hi|lo: 512 chunks each
            int buf = i >> 9, idx = i & 511;
            int row = idx >> 2, ch = idx & 3;
            int ar;
            if (FIRST) ar = s_rows[row];                 // token index
            else { ar = row0 + row; if (ar >= NTOK) ar = NTOK - 1; }
            const bf16* src = (buf ? Alo : Ahi) + (size_t)ar * KDIM + k0 + ch * 8;
            cpasync16(st + (buf ? A_LO : A_HI) + swA(row, ch), src);
        }
        #pragma unroll
        for (int i = tid; i < 1024; i += 256) {          // B hi|lo: [32 k][128 n]
            int buf = i >> 9, idx = i & 511;
            int kr = idx >> 4, ch = idx & 15;
            const bf16* src = (buf ? Blo : Bhi) + (size_t)(k0 + kr) * NDIM + n0 + ch * 8;
            cpasync16(st + (buf ? B_LO : B_HI) + swB(kr, ch), src);
        }
        asm volatile("cp.async.commit_group;" ::: "memory");
    };

    load_stage(0, 0);
    load_stage(1, 1);

    int wm = (wid >> 2) * 64;   // warp M offset
    int wn = (wid & 3) * 32;    // warp N offset

    // B ldmatrix.trans lane addressing
    int grp = lane >> 3, rit = lane & 7;
    int b_kadd = (grp & 1) * 8 + rit;
    int b_nsub = (grp >> 1) * 8;
    int a_r16 = lane & 15, a_chsel = lane >> 4;

    float d[4][4][4];
    #pragma unroll
    for (int a = 0; a < 4; a++)
        #pragma unroll
        for (int b = 0; b < 4; b++)
            #pragma unroll
            for (int c = 0; c < 4; c++) d[a][b][c] = 0.f;

    for (int c = 0; c < NCH; c++) {
        asm volatile("cp.async.wait_group 1;" ::: "memory");
        __syncthreads();
        if (c + 2 < NCH) load_stage((c + 2) % NSTAGE, c + 2);
        else asm volatile("cp.async.commit_group;" ::: "memory");

        uint32_t st = stage0 + (c % NSTAGE) * STAGE_BYTES;
        #pragma unroll
        for (int s = 0; s < 2; s++) {
            uint32_t bh[2][4], bl[2][4];
            int kl = s * 16 + b_kadd;
            #pragma unroll
            for (int nt = 0; nt < 2; nt++) {
                int nch = (wn + nt * 16 + b_nsub) >> 3;
                uint32_t off = swB(kl, nch);
                ldm4t(bh[nt], st + B_HI + off);
                ldm4t(bl[nt], st + B_LO + off);
            }
            int ach = s * 2 + a_chsel;
            #pragma unroll
            for (int mt = 0; mt < 4; mt++) {
                uint32_t ah[4], al[4];
                int row = wm + mt * 16 + a_r16;
                uint32_t off = swA(row, ach);
                ldm4(ah, st + A_HI + off);
                ldm4(al, st + A_LO + off);
                #pragma unroll
                for (int j = 0; j < 4; j++) {
                    int nt = j >> 1, sl = j & 1;
                    mma16816(d[mt][j], ah, bh[nt][sl * 2], bh[nt][sl * 2 + 1]);
                    mma16816(d[mt][j], ah, bl[nt][sl * 2], bl[nt][sl * 2 + 1]);
                    mma16816(d[mt][j], al, bh[nt][sl * 2], bh[nt][sl * 2 + 1]);
                }
            }
        }
    }

    // epilogue
    int r4 = lane >> 2, c2 = (lane & 3) * 2;
    #pragma unroll
    for (int mt = 0; mt < 4; mt++) {
        #pragma unroll
        for (int half = 0; half < 2; half++) {
            int lr = wm + mt * 16 + r4 + half * 8;
            int grow = row0 + lr;
            if (grow >= rend) continue;
            int tok = s_rows[lr];
            #pragma unroll
            for (int j = 0; j < 4; j++) {
                int col = wn + j * 8 + c2;
                float v0 = d[mt][j][half * 2 + 0] + s_bias[col];
                float v1 = d[mt][j][half * 2 + 1] + s_bias[col + 1];
                if (FIRST) {
                    v0 = 0.5f * v0 * (1.0f + erff(v0 * 0.70710678118654752440f));
                    v1 = 0.5f * v1 * (1.0f + erff(v1 * 0.70710678118654752440f));
                    bf16 h0, h1, l0, l1;
                    split2(v0, h0, l0); split2(v1, h1, l1);
                    *(uint32_t*)(g_hhi + (size_t)grow * NDIM + n0 + col) = pack2(h0, h1);
                    *(uint32_t*)(g_hlo + (size_t)grow * NDIM + n0 + col) = pack2(l0, l1);
                } else {
                    float2 v = make_float2(v0, v1);
                    *(float2*)(Cout + (size_t)tok * NDIM + n0 + col) = v;
                }
            }
        }
    }
}

// ---------------------------------------------------------------------------
extern "C" void kernel_launch(void* const* d_in, const int* in_sizes, int n_in,
                              void* d_out, int out_size)
{
    const float* x   = (const float*)d_in[0];
    const float* rw  = (const float*)d_in[1];
    const float* rb  = (const float*)d_in[2];
    const float* w1  = (const float*)d_in[3];
    const float* b1  = (const float*)d_in[4];
    const float* w2  = (const float*)d_in[5];
    const float* b2  = (const float*)d_in[6];
    const float* sw1 = (const float*)d_in[7];
    const float* sb1 = (const float*)d_in[8];
    const float* sw2 = (const float*)d_in[9];
    const float* sb2 = (const float*)d_in[10];
    float* out = (float*)d_out;

    cudaFuncSetAttribute(moe_gemm_mma<NH, NF, true>,
                         cudaFuncAttributeMaxDynamicSharedMemorySize, SMEMSZ);
    cudaFuncSetAttribute(moe_gemm_mma<NF, NH, false>,
                         cudaFuncAttributeMaxDynamicSharedMemorySize, SMEMSZ);

    router_kernel<<<NTOK, 256>>>(x, rw, rb);
    assign_kernel<<<1, 320>>>();
    convert_w_kernel<<<dim3(512, 2, NG), 256>>>(w1, sw1, w2, sw2);
    // GEMM1: grouped x @ w1 -> gelu -> g_h (hi/lo)
    moe_gemm_mma<NH, NF, true ><<<dim3(NF / NTILE, 41), 256, SMEMSZ>>>(b1, sb1, nullptr);
    // GEMM2: g_h @ w2 -> scatter to out
    moe_gemm_mma<NF, NH, false><<<dim3(NH / NTILE, 41), 256, SMEMSZ>>>(b2, sb2, out);
}